// round 4
// baseline (speedup 1.0000x reference)
#include <cuda_runtime.h>
#include <cstdint>

#define NN   50000
#define NE   600000
#define NT   (NE + NN)     // edges + self loops = 650000
#define D    128

// ---------------- device scratch (static, no runtime alloc) ----------------
__device__ float g_bufA[(size_t)NN * D];
__device__ float g_bufB[(size_t)NN * D];
__device__ float g_bufC[(size_t)NN * D];
__device__ float g_bufD[(size_t)NN * D];
__device__ int   g_col[NT];
__device__ float g_ew[NT];
__device__ int   g_rowptr[NN + 1];
__device__ int   g_deg[NN];
__device__ int   g_cursor[NN];
__device__ float g_dinv[NN];

// ---------------- CSR build ----------------
__global__ void init_kernel() {
    int v = blockIdx.x * blockDim.x + threadIdx.x;
    if (v < NN) { g_deg[v] = 1; g_cursor[v] = 0; }   // deg starts at 1 (self loop)
}

__global__ void count_kernel(const int* __restrict__ dst) {
    int e = blockIdx.x * blockDim.x + threadIdx.x;
    if (e < NE) atomicAdd(&g_deg[dst[e]], 1);
}

// single-block exclusive scan over degrees -> row_ptr; also d^{-1/2}
__global__ void scan_kernel() {
    const int T = 1024;
    const int CHUNK = (NN + T - 1) / T;   // 49
    int tid = threadIdx.x;
    int start = tid * CHUNK;
    int end = start + CHUNK; if (end > NN) end = NN;

    int s = 0;
    for (int i = start; i < end; ++i) s += g_deg[i];

    __shared__ int part[1024];
    part[tid] = s;
    __syncthreads();
    // Hillis-Steele inclusive scan
    for (int off = 1; off < T; off <<= 1) {
        int v = (tid >= off) ? part[tid - off] : 0;
        __syncthreads();
        part[tid] += v;
        __syncthreads();
    }
    int run = part[tid] - s;   // exclusive prefix
    for (int i = start; i < end; ++i) {
        g_rowptr[i] = run;
        run += g_deg[i];
        g_dinv[i] = rsqrtf((float)g_deg[i]);  // deg >= 1 always (self loop)
    }
    if (tid == T - 1) g_rowptr[NN] = part[T - 1];
}

__global__ void scatter_kernel(const int* __restrict__ src, const int* __restrict__ dst) {
    int e = blockIdx.x * blockDim.x + threadIdx.x;
    if (e >= NT) return;
    int s, d;
    if (e < NE) { s = src[e]; d = dst[e]; }
    else        { s = d = e - NE; }          // self loop
    int pos = g_rowptr[d] + atomicAdd(&g_cursor[d], 1);
    g_col[pos] = s;
    g_ew[pos]  = g_dinv[s] * g_dinv[d];
}

// ---------------- input linear: feat = w * lin_w + lin_b ----------------
__global__ void feat_kernel(const float* __restrict__ w,
                            const float* __restrict__ lw,
                            const float* __restrict__ lb) {
    int i = blockIdx.x * blockDim.x + threadIdx.x;   // over NN*32 float4s
    if (i >= NN * (D / 4)) return;
    int v  = i >> 5;
    int d4 = i & 31;
    float s = __ldg(w + v);
    float4 a = __ldg((const float4*)lw + d4);
    float4 b = __ldg((const float4*)lb + d4);
    float4 r;
    r.x = fmaf(s, a.x, b.x); r.y = fmaf(s, a.y, b.y);
    r.z = fmaf(s, a.z, b.z); r.w = fmaf(s, a.w, b.w);
    ((float4*)g_bufA)[i] = r;
}

// ---------------- SpMM: out = alpha * (A_norm @ X) [+ beta*aux] ----------------
// mode 0: X1 = -spmm(X0)           -> in = X0,  out = B
// mode 1: X2 = -2*spmm(X1) - X0    -> in = B,   out = C, aux = X0
__global__ void spmm_kernel(int mode, int flip) {
    const float* X0 = flip ? g_bufD : g_bufA;
    const float* X; float* out; const float* aux; float alpha;
    if (mode == 0) { X = X0;     out = g_bufB; aux = nullptr; alpha = -1.f; }
    else           { X = g_bufB; out = g_bufC; aux = X0;      alpha = -2.f; }

    int warp = (blockIdx.x * blockDim.x + threadIdx.x) >> 5;
    if (warp >= NN) return;
    int lane = threadIdx.x & 31;

    int beg = g_rowptr[warp];
    int end = g_rowptr[warp + 1];

    float4 acc = make_float4(0.f, 0.f, 0.f, 0.f);
    int p = beg;
    // unroll by 2 for MLP
    for (; p + 1 < end; p += 2) {
        int   c0 = __ldg(g_col + p);
        int   c1 = __ldg(g_col + p + 1);
        float w0 = __ldg(g_ew + p);
        float w1 = __ldg(g_ew + p + 1);
        float4 x0 = __ldg((const float4*)(X + (size_t)c0 * D) + lane);
        float4 x1 = __ldg((const float4*)(X + (size_t)c1 * D) + lane);
        acc.x = fmaf(w0, x0.x, acc.x); acc.y = fmaf(w0, x0.y, acc.y);
        acc.z = fmaf(w0, x0.z, acc.z); acc.w = fmaf(w0, x0.w, acc.w);
        acc.x = fmaf(w1, x1.x, acc.x); acc.y = fmaf(w1, x1.y, acc.y);
        acc.z = fmaf(w1, x1.z, acc.z); acc.w = fmaf(w1, x1.w, acc.w);
    }
    if (p < end) {
        int   c0 = __ldg(g_col + p);
        float w0 = __ldg(g_ew + p);
        float4 x0 = __ldg((const float4*)(X + (size_t)c0 * D) + lane);
        acc.x = fmaf(w0, x0.x, acc.x); acc.y = fmaf(w0, x0.y, acc.y);
        acc.z = fmaf(w0, x0.z, acc.z); acc.w = fmaf(w0, x0.w, acc.w);
    }

    float4 r;
    r.x = alpha * acc.x; r.y = alpha * acc.y;
    r.z = alpha * acc.z; r.w = alpha * acc.w;
    if (aux) {
        float4 a = __ldg((const float4*)(aux + (size_t)warp * D) + lane);
        r.x -= a.x; r.y -= a.y; r.z -= a.z; r.w -= a.w;
    }
    ((float4*)(out + (size_t)warp * D))[lane] = r;
}

// ---------------- GEMM: Y = relu([X0|X1|X2] @ W + b), M=NN, K=384, N=128 ----
#define BM 128
#define BN 128
#define BK 16

__global__ __launch_bounds__(256, 1)
void gemm_kernel(const float* __restrict__ W, const float* __restrict__ bias, int flip) {
    const float* X0 = flip ? g_bufD : g_bufA;
    float*       Y  = flip ? g_bufA : g_bufD;

    __shared__ float As[BK][BM];
    __shared__ float Bs[BK][BN];

    int tid  = threadIdx.x;
    int row0 = blockIdx.x * BM;
    int tx = tid & 15;     // 16 col-threads * 8 cols
    int ty = tid >> 4;     // 16 row-threads * 8 rows

    float acc[8][8];
#pragma unroll
    for (int i = 0; i < 8; ++i)
#pragma unroll
        for (int j = 0; j < 8; ++j) acc[i][j] = 0.f;

    for (int kt = 0; kt < 384 / BK; ++kt) {
        int kk = kt * BK;
        const float* A = (kk < 128) ? X0 : ((kk < 256) ? (const float*)g_bufB
                                                       : (const float*)g_bufC);
        int kloc = kk & 127;

        // load A tile: 128x16 = 512 float4, 2 per thread
#pragma unroll
        for (int i = 0; i < 2; ++i) {
            int idx = tid + i * 256;
            int r   = idx >> 2;        // 0..127
            int c4  = idx & 3;         // 0..3
            int grow = row0 + r;
            float4 v = make_float4(0.f, 0.f, 0.f, 0.f);
            if (grow < NN)
                v = *(const float4*)(A + (size_t)grow * D + kloc + c4 * 4);
            As[c4 * 4 + 0][r] = v.x;
            As[c4 * 4 + 1][r] = v.y;
            As[c4 * 4 + 2][r] = v.z;
            As[c4 * 4 + 3][r] = v.w;
        }
        // load B tile: 16x128 = 512 float4, 2 per thread
#pragma unroll
        for (int i = 0; i < 2; ++i) {
            int idx = tid + i * 256;
            int k  = idx >> 5;         // 0..15
            int n4 = idx & 31;         // 0..31
            float4 v = *(const float4*)(W + (size_t)(kk + k) * BN + n4 * 4);
            *(float4*)(&Bs[k][n4 * 4]) = v;
        }
        __syncthreads();

#pragma unroll
        for (int k = 0; k < BK; ++k) {
            float4 a0 = *(const float4*)(&As[k][ty * 8]);
            float4 a1 = *(const float4*)(&As[k][ty * 8 + 4]);
            float4 b0 = *(const float4*)(&Bs[k][tx * 8]);
            float4 b1 = *(const float4*)(&Bs[k][tx * 8 + 4]);
            float a[8] = {a0.x, a0.y, a0.z, a0.w, a1.x, a1.y, a1.z, a1.w};
            float b[8] = {b0.x, b0.y, b0.z, b0.w, b1.x, b1.y, b1.z, b1.w};
#pragma unroll
            for (int i = 0; i < 8; ++i)
#pragma unroll
                for (int j = 0; j < 8; ++j)
                    acc[i][j] = fmaf(a[i], b[j], acc[i][j]);
        }
        __syncthreads();
    }

    // epilogue: + bias, relu, store
#pragma unroll
    for (int i = 0; i < 8; ++i) {
        int grow = row0 + ty * 8 + i;
        if (grow < NN) {
#pragma unroll
            for (int j4 = 0; j4 < 2; ++j4) {
                int col = tx * 8 + j4 * 4;
                float4 bb = *(const float4*)(bias + col);
                float4 v;
                v.x = fmaxf(acc[i][j4 * 4 + 0] + bb.x, 0.f);
                v.y = fmaxf(acc[i][j4 * 4 + 1] + bb.y, 0.f);
                v.z = fmaxf(acc[i][j4 * 4 + 2] + bb.z, 0.f);
                v.w = fmaxf(acc[i][j4 * 4 + 3] + bb.w, 0.f);
                *(float4*)(Y + (size_t)grow * D + col) = v;
            }
        }
    }
}

// ---------------- prediction head: out[v] = emb[v] . pred_w + pred_b -------
__global__ void pred_kernel(const float* __restrict__ pw,
                            const float* __restrict__ pb,
                            float* __restrict__ out) {
    int warp = (blockIdx.x * blockDim.x + threadIdx.x) >> 5;
    if (warp >= NN) return;
    int lane = threadIdx.x & 31;
    float4 e = ((const float4*)(g_bufD + (size_t)warp * D))[lane];
    float4 p = __ldg((const float4*)pw + lane);
    float s = e.x * p.x + e.y * p.y + e.z * p.z + e.w * p.w;
#pragma unroll
    for (int o = 16; o; o >>= 1) s += __shfl_xor_sync(0xffffffffu, s, o);
    if (lane == 0) out[warp] = s + __ldg(pb);
}

// ---------------- host launch ----------------
extern "C" void kernel_launch(void* const* d_in, const int* in_sizes, int n_in,
                              void* d_out, int out_size) {
    const float* weights = (const float*)d_in[0];
    const int*   src     = (const int*)d_in[1];
    const int*   dst     = (const int*)d_in[2];
    const float* lin_w   = (const float*)d_in[3];
    const float* lin_b   = (const float*)d_in[4];
    const float* cheb_ws = (const float*)d_in[5];
    const float* cheb_bs = (const float*)d_in[6];
    const float* pred_w  = (const float*)d_in[7];
    const float* pred_b  = (const float*)d_in[8];
    float* out = (float*)d_out;

    // CSR build
    init_kernel   <<<(NN + 255) / 256, 256>>>();
    count_kernel  <<<(NE + 255) / 256, 256>>>(dst);
    scan_kernel   <<<1, 1024>>>();
    scatter_kernel<<<(NT + 255) / 256, 256>>>(src, dst);

    // input linear
    feat_kernel<<<(NN * (D / 4) + 255) / 256, 256>>>(weights, lin_w, lin_b);

    const int spmm_blocks = (NN * 32 + 255) / 256;   // one warp per node
    const int gemm_blocks = (NN + BM - 1) / BM;

    for (int l = 0; l < 3; ++l) {
        int flip = (l == 1);
        spmm_kernel<<<spmm_blocks, 256>>>(0, flip);                       // X1 = -A~ X0
        spmm_kernel<<<spmm_blocks, 256>>>(1, flip);                       // X2 = -2 A~ X1 - X0
        gemm_kernel<<<gemm_blocks, 256>>>(cheb_ws + (size_t)l * 384 * 128,
                                          cheb_bs + (size_t)l * 128, flip);
        // inter-layer leaky_relu(relu(x)) == relu(x): no-op, skipped
    }

    pred_kernel<<<spmm_blocks, 256>>>(pred_w, pred_b, out);
}

// round 6
// speedup vs baseline: 1.3830x; 1.3830x over previous
#include <cuda_runtime.h>
#include <cuda_bf16.h>
#include <cstdint>

#define NN   50000
#define NE   600000
#define NT   (NE + NN)     // edges + self loops = 650000
#define D    128

// ---------------- device scratch (static, no runtime alloc) ----------------
__device__ float g_bufA[(size_t)NN * D];
__device__ float g_bufB[(size_t)NN * D];
__device__ float g_bufC[(size_t)NN * D];
__device__ float g_bufD[(size_t)NN * D];
__device__ int   g_col[NT];
__device__ float g_ew[NT];
__device__ int   g_rowptr[NN + 1];
__device__ int   g_deg[NN];
__device__ int   g_cursor[NN];
__device__ float g_dinv[NN];

// ---------------- CSR build ----------------
__global__ void init_kernel() {
    int v = blockIdx.x * blockDim.x + threadIdx.x;
    if (v < NN) { g_deg[v] = 1; g_cursor[v] = 0; }   // deg starts at 1 (self loop)
}

__global__ void count_kernel(const int* __restrict__ dst) {
    int e = blockIdx.x * blockDim.x + threadIdx.x;
    if (e < NE) atomicAdd(&g_deg[dst[e]], 1);
}

__global__ void scan_kernel() {
    const int T = 1024;
    const int CHUNK = (NN + T - 1) / T;
    int tid = threadIdx.x;
    int start = tid * CHUNK;
    int end = start + CHUNK; if (end > NN) end = NN;
    int s = 0;
    for (int i = start; i < end; ++i) s += g_deg[i];
    __shared__ int part[1024];
    part[tid] = s;
    __syncthreads();
    for (int off = 1; off < T; off <<= 1) {
        int v = (tid >= off) ? part[tid - off] : 0;
        __syncthreads();
        part[tid] += v;
        __syncthreads();
    }
    int run = part[tid] - s;
    for (int i = start; i < end; ++i) {
        g_rowptr[i] = run;
        run += g_deg[i];
        g_dinv[i] = rsqrtf((float)g_deg[i]);
    }
    if (tid == T - 1) g_rowptr[NN] = part[T - 1];
}

__global__ void scatter_kernel(const int* __restrict__ src, const int* __restrict__ dst) {
    int e = blockIdx.x * blockDim.x + threadIdx.x;
    if (e >= NT) return;
    int s, d;
    if (e < NE) { s = src[e]; d = dst[e]; }
    else        { s = d = e - NE; }
    int pos = g_rowptr[d] + atomicAdd(&g_cursor[d], 1);
    g_col[pos] = s;
    g_ew[pos]  = g_dinv[s] * g_dinv[d];
}

// ---------------- input linear ----------------
__global__ void feat_kernel(const float* __restrict__ w,
                            const float* __restrict__ lw,
                            const float* __restrict__ lb) {
    int i = blockIdx.x * blockDim.x + threadIdx.x;
    if (i >= NN * (D / 4)) return;
    int v  = i >> 5;
    int d4 = i & 31;
    float s = __ldg(w + v);
    float4 a = __ldg((const float4*)lw + d4);
    float4 b = __ldg((const float4*)lb + d4);
    float4 r;
    r.x = fmaf(s, a.x, b.x); r.y = fmaf(s, a.y, b.y);
    r.z = fmaf(s, a.z, b.z); r.w = fmaf(s, a.w, b.w);
    ((float4*)g_bufA)[i] = r;
}

// ---------------- SpMM ----------------
__global__ void spmm_kernel(int mode, int flip) {
    const float* X0 = flip ? g_bufD : g_bufA;
    const float* X; float* out; const float* aux; float alpha;
    if (mode == 0) { X = X0;     out = g_bufB; aux = nullptr; alpha = -1.f; }
    else           { X = g_bufB; out = g_bufC; aux = X0;      alpha = -2.f; }

    int warp = (blockIdx.x * blockDim.x + threadIdx.x) >> 5;
    if (warp >= NN) return;
    int lane = threadIdx.x & 31;
    int beg = g_rowptr[warp];
    int end = g_rowptr[warp + 1];

    float4 acc = make_float4(0.f, 0.f, 0.f, 0.f);
    int p = beg;
    for (; p + 1 < end; p += 2) {
        int   c0 = __ldg(g_col + p);
        int   c1 = __ldg(g_col + p + 1);
        float w0 = __ldg(g_ew + p);
        float w1 = __ldg(g_ew + p + 1);
        float4 x0 = __ldg((const float4*)(X + (size_t)c0 * D) + lane);
        float4 x1 = __ldg((const float4*)(X + (size_t)c1 * D) + lane);
        acc.x = fmaf(w0, x0.x, acc.x); acc.y = fmaf(w0, x0.y, acc.y);
        acc.z = fmaf(w0, x0.z, acc.z); acc.w = fmaf(w0, x0.w, acc.w);
        acc.x = fmaf(w1, x1.x, acc.x); acc.y = fmaf(w1, x1.y, acc.y);
        acc.z = fmaf(w1, x1.z, acc.z); acc.w = fmaf(w1, x1.w, acc.w);
    }
    if (p < end) {
        int   c0 = __ldg(g_col + p);
        float w0 = __ldg(g_ew + p);
        float4 x0 = __ldg((const float4*)(X + (size_t)c0 * D) + lane);
        acc.x = fmaf(w0, x0.x, acc.x); acc.y = fmaf(w0, x0.y, acc.y);
        acc.z = fmaf(w0, x0.z, acc.z); acc.w = fmaf(w0, x0.w, acc.w);
    }
    float4 r;
    r.x = alpha * acc.x; r.y = alpha * acc.y;
    r.z = alpha * acc.z; r.w = alpha * acc.w;
    if (aux) {
        float4 a = __ldg((const float4*)(aux + (size_t)warp * D) + lane);
        r.x -= a.x; r.y -= a.y; r.z -= a.z; r.w -= a.w;
    }
    ((float4*)(out + (size_t)warp * D))[lane] = r;
}

// ======================= mma.sync bf16 GEMM (3-term split) =======================
// Y[128-tile, 128] = relu([X0|X1|X2] @ W + b), fp32 in/out.
// x = hi + lo (bf16 split); x@w ~= Ah@Bh + Ah@Bl + Al@Bh (lo*lo term ~2^-16 dropped).
// 8 warps, warp tile 64x32, m16n8k16 HMMA. K processed in 6 chunks of 64
// (3 sources x 2). Smem rows padded to 72 bf16 (36 words) -> conflict-free frags.

#define KC       64
#define ROW_W    36                       // row stride in 32-bit words (72 bf16)
#define BUF_W    (128 * ROW_W)            // 4608 words = 18432 B per buffer
#define GSMEM    (4 * BUF_W * 4)          // 73728 B dynamic smem

__device__ __forceinline__ void mma_bf16(float* acc,
                                         uint32_t a0, uint32_t a1, uint32_t a2, uint32_t a3,
                                         uint32_t b0, uint32_t b1) {
    asm volatile(
        "mma.sync.aligned.m16n8k16.row.col.f32.bf16.bf16.f32 "
        "{%0,%1,%2,%3}, {%4,%5,%6,%7}, {%8,%9}, {%0,%1,%2,%3};"
        : "+f"(acc[0]), "+f"(acc[1]), "+f"(acc[2]), "+f"(acc[3])
        : "r"(a0), "r"(a1), "r"(a2), "r"(a3), "r"(b0), "r"(b1));
}

__device__ __forceinline__ uint32_t pack2(float a, float b) {
    __nv_bfloat162 h = __floats2bfloat162_rn(a, b);
    return *reinterpret_cast<uint32_t*>(&h);
}

__global__ __launch_bounds__(256, 1)
void gemm_mma_kernel(const float* __restrict__ W, const float* __restrict__ bias, int flip) {
    extern __shared__ uint32_t dsm[];
    uint32_t* Ah = dsm;
    uint32_t* Al = Ah + BUF_W;
    uint32_t* Bh = Al + BUF_W;
    uint32_t* Bl = Bh + BUF_W;

    const float* X0 = flip ? g_bufD : g_bufA;
    float*       Y  = flip ? g_bufA : g_bufD;

    int tid = threadIdx.x;
    int wid = tid >> 5;
    int lane = tid & 31;
    int g   = lane >> 2;       // group id (0..7)
    int tig = lane & 3;        // thread in group
    int row0 = blockIdx.x * 128;

    int m0w = (wid >> 2) * 64; // warp m offset (0 or 64)
    int n0w = (wid & 3) * 32;  // warp n offset

    float acc[4][4][4];
#pragma unroll
    for (int mi = 0; mi < 4; ++mi)
#pragma unroll
        for (int ni = 0; ni < 4; ++ni)
#pragma unroll
            for (int q = 0; q < 4; ++q) acc[mi][ni][q] = 0.f;

    for (int src = 0; src < 3; ++src) {
        const float* A = (src == 0) ? X0 : ((src == 1) ? (const float*)g_bufB
                                                       : (const float*)g_bufC);
        for (int kc = 0; kc < 2; ++kc) {
            int kk = kc * KC;

            // ---- convert A chunk [128 x 64] fp32 -> bf16 hi/lo ----
#pragma unroll
            for (int i = 0; i < 8; ++i) {
                int idx = tid + i * 256;           // 2048 float4s
                int r   = idx >> 4;                // 0..127
                int c4  = idx & 15;                // k0 = c4*4
                int grow = row0 + r;
                float4 v = make_float4(0.f, 0.f, 0.f, 0.f);
                if (grow < NN)
                    v = *(const float4*)(A + (size_t)grow * D + kk + c4 * 4);
                __nv_bfloat16 h0 = __float2bfloat16_rn(v.x);
                __nv_bfloat16 h1 = __float2bfloat16_rn(v.y);
                __nv_bfloat16 h2 = __float2bfloat16_rn(v.z);
                __nv_bfloat16 h3 = __float2bfloat16_rn(v.w);
                int wo = r * ROW_W + c4 * 2;
                Ah[wo]     = pack2(__bfloat162float(h0), __bfloat162float(h1));
                Ah[wo + 1] = pack2(__bfloat162float(h2), __bfloat162float(h3));
                Al[wo]     = pack2(v.x - __bfloat162float(h0), v.y - __bfloat162float(h1));
                Al[wo + 1] = pack2(v.z - __bfloat162float(h2), v.w - __bfloat162float(h3));
            }

            // ---- convert+transpose B chunk: Bsm[n][k] = W[src*128+kk+k][n] ----
            const float* Wc = W + ((size_t)src * 128 + kk) * 128;
#pragma unroll
            for (int i = 0; i < 4; ++i) {
                int idx = tid + i * 256;           // 1024 iters: (k2, n4)
                int k2 = idx >> 5;                 // 0..31 (k pair)
                int n4 = idx & 31;                 // 0..31 (n group of 4)
                float4 va = *(const float4*)(Wc + (size_t)(2 * k2)     * 128 + n4 * 4);
                float4 vb = *(const float4*)(Wc + (size_t)(2 * k2 + 1) * 128 + n4 * 4);
                const float* pa = &va.x;
                const float* pb = &vb.x;
#pragma unroll
                for (int j = 0; j < 4; ++j) {
                    int n = n4 * 4 + j;
                    float w0 = pa[j], w1 = pb[j];
                    __nv_bfloat16 h0 = __float2bfloat16_rn(w0);
                    __nv_bfloat16 h1 = __float2bfloat16_rn(w1);
                    int wo = n * ROW_W + k2;
                    Bh[wo] = pack2(__bfloat162float(h0), __bfloat162float(h1));
                    Bl[wo] = pack2(w0 - __bfloat162float(h0), w1 - __bfloat162float(h1));
                }
            }
            __syncthreads();

            // ---- MMA: 3 split terms x 4 k16-steps x (4x4 frags) ----
#pragma unroll
            for (int term = 0; term < 3; ++term) {
                const uint32_t* As = (term == 2) ? Al : Ah;
                const uint32_t* Bs = (term == 1) ? Bl : Bh;
#pragma unroll
                for (int ks = 0; ks < 4; ++ks) {
                    int kw = ks * 8;   // k16 offset in words
                    uint32_t af[4][4], bfr[4][2];
#pragma unroll
                    for (int mi = 0; mi < 4; ++mi) {
                        const uint32_t* p = As + (m0w + mi * 16 + g) * ROW_W + kw + tig;
                        af[mi][0] = p[0];
                        af[mi][1] = p[8 * ROW_W];
                        af[mi][2] = p[4];
                        af[mi][3] = p[8 * ROW_W + 4];
                    }
#pragma unroll
                    for (int ni = 0; ni < 4; ++ni) {
                        const uint32_t* p = Bs + (n0w + ni * 8 + g) * ROW_W + kw + tig;
                        bfr[ni][0] = p[0];
                        bfr[ni][1] = p[4];
                    }
#pragma unroll
                    for (int mi = 0; mi < 4; ++mi)
#pragma unroll
                        for (int ni = 0; ni < 4; ++ni)
                            mma_bf16(acc[mi][ni],
                                     af[mi][0], af[mi][1], af[mi][2], af[mi][3],
                                     bfr[ni][0], bfr[ni][1]);
                }
            }
            __syncthreads();
        }
    }

    // ---- epilogue: + bias, relu, store ----
#pragma unroll
    for (int mi = 0; mi < 4; ++mi) {
        int r0 = row0 + m0w + mi * 16 + g;
        int r1 = r0 + 8;
#pragma unroll
        for (int ni = 0; ni < 4; ++ni) {
            int c = n0w + ni * 8 + 2 * tig;
            float2 bb = *(const float2*)(bias + c);
            if (r0 < NN) {
                float2 v;
                v.x = fmaxf(acc[mi][ni][0] + bb.x, 0.f);
                v.y = fmaxf(acc[mi][ni][1] + bb.y, 0.f);
                *(float2*)(Y + (size_t)r0 * D + c) = v;
            }
            if (r1 < NN) {
                float2 v;
                v.x = fmaxf(acc[mi][ni][2] + bb.x, 0.f);
                v.y = fmaxf(acc[mi][ni][3] + bb.y, 0.f);
                *(float2*)(Y + (size_t)r1 * D + c) = v;
            }
        }
    }
}

// ---------------- prediction head ----------------
__global__ void pred_kernel(const float* __restrict__ pw,
                            const float* __restrict__ pb,
                            float* __restrict__ out) {
    int warp = (blockIdx.x * blockDim.x + threadIdx.x) >> 5;
    if (warp >= NN) return;
    int lane = threadIdx.x & 31;
    float4 e = ((const float4*)(g_bufD + (size_t)warp * D))[lane];
    float4 p = __ldg((const float4*)pw + lane);
    float s = e.x * p.x + e.y * p.y + e.z * p.z + e.w * p.w;
#pragma unroll
    for (int o = 16; o; o >>= 1) s += __shfl_xor_sync(0xffffffffu, s, o);
    if (lane == 0) out[warp] = s + __ldg(pb);
}

// ---------------- host launch ----------------
extern "C" void kernel_launch(void* const* d_in, const int* in_sizes, int n_in,
                              void* d_out, int out_size) {
    const float* weights = (const float*)d_in[0];
    const int*   src     = (const int*)d_in[1];
    const int*   dst     = (const int*)d_in[2];
    const float* lin_w   = (const float*)d_in[3];
    const float* lin_b   = (const float*)d_in[4];
    const float* cheb_ws = (const float*)d_in[5];
    const float* cheb_bs = (const float*)d_in[6];
    const float* pred_w  = (const float*)d_in[7];
    const float* pred_b  = (const float*)d_in[8];
    float* out = (float*)d_out;

    static int smem_set = 0;
    if (!smem_set) {
        cudaFuncSetAttribute(gemm_mma_kernel,
                             cudaFuncAttributeMaxDynamicSharedMemorySize, GSMEM);
        smem_set = 1;
    }

    // CSR build
    init_kernel   <<<(NN + 255) / 256, 256>>>();
    count_kernel  <<<(NE + 255) / 256, 256>>>(dst);
    scan_kernel   <<<1, 1024>>>();
    scatter_kernel<<<(NT + 255) / 256, 256>>>(src, dst);

    // input linear
    feat_kernel<<<(NN * (D / 4) + 255) / 256, 256>>>(weights, lin_w, lin_b);

    const int spmm_blocks = (NN * 32 + 255) / 256;   // one warp per node
    const int gemm_blocks = (NN + 127) / 128;        // 391

    for (int l = 0; l < 3; ++l) {
        int flip = (l == 1);
        spmm_kernel<<<spmm_blocks, 256>>>(0, flip);   // X1 = -A~ X0
        spmm_kernel<<<spmm_blocks, 256>>>(1, flip);   // X2 = -2 A~ X1 - X0
        gemm_mma_kernel<<<gemm_blocks, 256, GSMEM>>>(
            cheb_ws + (size_t)l * 384 * 128, cheb_bs + (size_t)l * 128, flip);
        // inter-layer leaky_relu(relu(x)) == relu(x): no-op, skipped
    }

    pred_kernel<<<spmm_blocks, 256>>>(pred_w, pred_b, out);
}

// round 8
// speedup vs baseline: 1.6275x; 1.1767x over previous
#include <cuda_runtime.h>
#include <cuda_bf16.h>
#include <cstdint>

#define NN   50000
#define NE   600000
#define NT   (NE + NN)     // edges + self loops = 650000
#define D    128

// ---------------- device scratch (static, no runtime alloc) ----------------
__device__ float g_bufA[(size_t)NN * D];
__device__ float g_bufB[(size_t)NN * D];
__device__ float g_bufC[(size_t)NN * D];
__device__ float g_bufD[(size_t)NN * D];
__device__ int2  g_colew[NT];            // packed {col, bitcast(weight)}
__device__ int   g_rowptr[NN + 1];
__device__ int   g_deg[NN];
__device__ int   g_cursor[NN];
__device__ float g_dinv[NN];
// W precomputed as bf16 hi/lo, transposed: [layer][n(128)][k(384)]
__device__ __nv_bfloat16 g_Whi[3 * 128 * 384];
__device__ __nv_bfloat16 g_Wlo[3 * 128 * 384];

// ---------------- CSR build ----------------
__global__ void init_kernel() {
    int v = blockIdx.x * blockDim.x + threadIdx.x;
    if (v < NN) { g_deg[v] = 1; g_cursor[v] = 0; }   // deg starts at 1 (self loop)
}

__global__ void count_kernel(const int* __restrict__ dst) {
    int e = blockIdx.x * blockDim.x + threadIdx.x;
    if (e < NE) atomicAdd(&g_deg[dst[e]], 1);
}

__global__ void scan_kernel() {
    const int T = 1024;
    const int CHUNK = (NN + T - 1) / T;
    int tid = threadIdx.x;
    int start = tid * CHUNK;
    int end = start + CHUNK; if (end > NN) end = NN;
    int s = 0;
    for (int i = start; i < end; ++i) s += g_deg[i];
    __shared__ int part[1024];
    part[tid] = s;
    __syncthreads();
    for (int off = 1; off < T; off <<= 1) {
        int v = (tid >= off) ? part[tid - off] : 0;
        __syncthreads();
        part[tid] += v;
        __syncthreads();
    }
    int run = part[tid] - s;
    for (int i = start; i < end; ++i) {
        g_rowptr[i] = run;
        run += g_deg[i];
        g_dinv[i] = rsqrtf((float)g_deg[i]);
    }
    if (tid == T - 1) g_rowptr[NN] = part[T - 1];
}

__global__ void scatter_kernel(const int* __restrict__ src, const int* __restrict__ dst) {
    int e = blockIdx.x * blockDim.x + threadIdx.x;
    if (e >= NT) return;
    int s, d;
    if (e < NE) { s = src[e]; d = dst[e]; }
    else        { s = d = e - NE; }
    int pos = g_rowptr[d] + atomicAdd(&g_cursor[d], 1);
    g_colew[pos] = make_int2(s, __float_as_int(g_dinv[s] * g_dinv[d]));
}

// ---------------- W -> bf16 hi/lo, transposed (once per call) ----------------
__global__ void wprep_kernel(const float* __restrict__ cheb_ws) {
    int i = blockIdx.x * blockDim.x + threadIdx.x;   // 3*384*128
    if (i >= 3 * 384 * 128) return;
    int l   = i / (384 * 128);
    int rem = i % (384 * 128);
    int k = rem >> 7;      // 0..383
    int n = rem & 127;
    float w = __ldg(cheb_ws + (size_t)l * 384 * 128 + (size_t)k * 128 + n);
    __nv_bfloat16 h = __float2bfloat16_rn(w);
    size_t o = ((size_t)l * 128 + n) * 384 + k;
    g_Whi[o] = h;
    g_Wlo[o] = __float2bfloat16_rn(w - __bfloat162float(h));
}

// ---------------- input linear ----------------
__global__ void feat_kernel(const float* __restrict__ w,
                            const float* __restrict__ lw,
                            const float* __restrict__ lb) {
    int i = blockIdx.x * blockDim.x + threadIdx.x;
    if (i >= NN * (D / 4)) return;
    int v  = i >> 5;
    int d4 = i & 31;
    float s = __ldg(w + v);
    float4 a = __ldg((const float4*)lw + d4);
    float4 b = __ldg((const float4*)lb + d4);
    float4 r;
    r.x = fmaf(s, a.x, b.x); r.y = fmaf(s, a.y, b.y);
    r.z = fmaf(s, a.z, b.z); r.w = fmaf(s, a.w, b.w);
    ((float4*)g_bufA)[i] = r;
}

// ---------------- SpMM ----------------
__global__ void spmm_kernel(int mode, int flip) {
    const float* X0 = flip ? g_bufD : g_bufA;
    const float* X; float* out; const float* aux; float alpha;
    if (mode == 0) { X = X0;     out = g_bufB; aux = nullptr; alpha = -1.f; }
    else           { X = g_bufB; out = g_bufC; aux = X0;      alpha = -2.f; }

    int warp = (blockIdx.x * blockDim.x + threadIdx.x) >> 5;
    if (warp >= NN) return;
    int lane = threadIdx.x & 31;
    int beg = g_rowptr[warp];
    int end = g_rowptr[warp + 1];

    float4 acc = make_float4(0.f, 0.f, 0.f, 0.f);
    int p = beg;
    for (; p + 3 < end; p += 4) {
        int2 e0 = __ldg(g_colew + p);
        int2 e1 = __ldg(g_colew + p + 1);
        int2 e2 = __ldg(g_colew + p + 2);
        int2 e3 = __ldg(g_colew + p + 3);
        float4 x0 = __ldg((const float4*)(X + (size_t)e0.x * D) + lane);
        float4 x1 = __ldg((const float4*)(X + (size_t)e1.x * D) + lane);
        float4 x2 = __ldg((const float4*)(X + (size_t)e2.x * D) + lane);
        float4 x3 = __ldg((const float4*)(X + (size_t)e3.x * D) + lane);
        float w0 = __int_as_float(e0.y);
        float w1 = __int_as_float(e1.y);
        float w2 = __int_as_float(e2.y);
        float w3 = __int_as_float(e3.y);
        acc.x = fmaf(w0, x0.x, acc.x); acc.y = fmaf(w0, x0.y, acc.y);
        acc.z = fmaf(w0, x0.z, acc.z); acc.w = fmaf(w0, x0.w, acc.w);
        acc.x = fmaf(w1, x1.x, acc.x); acc.y = fmaf(w1, x1.y, acc.y);
        acc.z = fmaf(w1, x1.z, acc.z); acc.w = fmaf(w1, x1.w, acc.w);
        acc.x = fmaf(w2, x2.x, acc.x); acc.y = fmaf(w2, x2.y, acc.y);
        acc.z = fmaf(w2, x2.z, acc.z); acc.w = fmaf(w2, x2.w, acc.w);
        acc.x = fmaf(w3, x3.x, acc.x); acc.y = fmaf(w3, x3.y, acc.y);
        acc.z = fmaf(w3, x3.z, acc.z); acc.w = fmaf(w3, x3.w, acc.w);
    }
    for (; p < end; ++p) {
        int2 e0 = __ldg(g_colew + p);
        float w0 = __int_as_float(e0.y);
        float4 x0 = __ldg((const float4*)(X + (size_t)e0.x * D) + lane);
        acc.x = fmaf(w0, x0.x, acc.x); acc.y = fmaf(w0, x0.y, acc.y);
        acc.z = fmaf(w0, x0.z, acc.z); acc.w = fmaf(w0, x0.w, acc.w);
    }
    float4 r;
    r.x = alpha * acc.x; r.y = alpha * acc.y;
    r.z = alpha * acc.z; r.w = alpha * acc.w;
    if (aux) {
        float4 a = __ldg((const float4*)(aux + (size_t)warp * D) + lane);
        r.x -= a.x; r.y -= a.y; r.z -= a.z; r.w -= a.w;
    }
    ((float4*)(out + (size_t)warp * D))[lane] = r;
}

// ======================= mma.sync bf16 GEMM (3-term split) =======================
// Y[128-tile, 128] = relu([X0|X1|X2] @ W + b), fp32 in/out.
// x = hi + lo (bf16 split); x@w ~= Ah@Bh + Ah@Bl + Al@Bh (lo*lo ~2^-16 dropped).
// 8 warps, warp tile 64x32, m16n8k16 HMMA. K in 6 chunks of 64 (3 sources x 2).
// B comes pre-split from g_Whi/g_Wlo (plain smem copy, no per-block conversion).
// Smem rows padded to 36 words (72 bf16) -> conflict-free fragment LDS.

#define KC       64
#define ROW_W    36
#define BUF_W    (128 * ROW_W)            // 4608 words per buffer
#define GSMEM    (4 * BUF_W * 4)          // 73728 B dynamic smem

__device__ __forceinline__ void mma_bf16(float* acc,
                                         uint32_t a0, uint32_t a1, uint32_t a2, uint32_t a3,
                                         uint32_t b0, uint32_t b1) {
    asm volatile(
        "mma.sync.aligned.m16n8k16.row.col.f32.bf16.bf16.f32 "
        "{%0,%1,%2,%3}, {%4,%5,%6,%7}, {%8,%9}, {%0,%1,%2,%3};"
        : "+f"(acc[0]), "+f"(acc[1]), "+f"(acc[2]), "+f"(acc[3])
        : "r"(a0), "r"(a1), "r"(a2), "r"(a3), "r"(b0), "r"(b1));
}

__device__ __forceinline__ uint32_t pack2(float a, float b) {
    __nv_bfloat162 h = __floats2bfloat162_rn(a, b);
    return *reinterpret_cast<uint32_t*>(&h);
}

__global__ __launch_bounds__(256, 1)
void gemm_mma_kernel(int layer, const float* __restrict__ bias, int flip) {
    extern __shared__ uint32_t dsm[];
    uint32_t* Ah = dsm;
    uint32_t* Al = Ah + BUF_W;
    uint32_t* Bh = Al + BUF_W;
    uint32_t* Bl = Bh + BUF_W;

    const float* X0 = flip ? g_bufD : g_bufA;
    float*       Y  = flip ? g_bufA : g_bufD;
    const __nv_bfloat16* WH = g_Whi + (size_t)layer * 128 * 384;
    const __nv_bfloat16* WL = g_Wlo + (size_t)layer * 128 * 384;

    int tid = threadIdx.x;
    int wid = tid >> 5;
    int lane = tid & 31;
    int g   = lane >> 2;
    int tig = lane & 3;
    int row0 = blockIdx.x * 128;

    int m0w = (wid >> 2) * 64;
    int n0w = (wid & 3) * 32;

    float acc[4][4][4];
#pragma unroll
    for (int mi = 0; mi < 4; ++mi)
#pragma unroll
        for (int ni = 0; ni < 4; ++ni)
#pragma unroll
            for (int q = 0; q < 4; ++q) acc[mi][ni][q] = 0.f;

    for (int src = 0; src < 3; ++src) {
        const float* A = (src == 0) ? X0 : ((src == 1) ? (const float*)g_bufB
                                                       : (const float*)g_bufC);
        for (int kc = 0; kc < 2; ++kc) {
            int kk = kc * KC;
            int kbase = src * 128 + kk;

            // ---- convert A chunk [128 x 64] fp32 -> bf16 hi/lo ----
#pragma unroll
            for (int i = 0; i < 8; ++i) {
                int idx = tid + i * 256;           // 2048 float4s
                int r   = idx >> 4;
                int c4  = idx & 15;
                int grow = row0 + r;
                float4 v = make_float4(0.f, 0.f, 0.f, 0.f);
                if (grow < NN)
                    v = *(const float4*)(A + (size_t)grow * D + kk + c4 * 4);
                __nv_bfloat16 h0 = __float2bfloat16_rn(v.x);
                __nv_bfloat16 h1 = __float2bfloat16_rn(v.y);
                __nv_bfloat16 h2 = __float2bfloat16_rn(v.z);
                __nv_bfloat16 h3 = __float2bfloat16_rn(v.w);
                int wo = r * ROW_W + c4 * 2;
                Ah[wo]     = pack2(__bfloat162float(h0), __bfloat162float(h1));
                Ah[wo + 1] = pack2(__bfloat162float(h2), __bfloat162float(h3));
                Al[wo]     = pack2(v.x - __bfloat162float(h0), v.y - __bfloat162float(h1));
                Al[wo + 1] = pack2(v.z - __bfloat162float(h2), v.w - __bfloat162float(h3));
            }

            // ---- copy pre-split B chunk [128 n x 64 k] from global bf16 ----
            // 128 rows x 8 uint4 (64 bf16) per row = 1024 transfers
#pragma unroll
            for (int i = 0; i < 4; ++i) {
                int idx = tid + i * 256;           // 0..1023 : (n, f4)
                int n  = idx >> 3;                 // 0..127
                int f4 = idx & 7;                  // 0..7 (uint4 = 8 bf16)
                uint4 vh = *(const uint4*)(WH + (size_t)n * 384 + kbase + f4 * 8);
                uint4 vl = *(const uint4*)(WL + (size_t)n * 384 + kbase + f4 * 8);
                *(uint4*)(Bh + n * ROW_W + f4 * 4) = vh;
                *(uint4*)(Bl + n * ROW_W + f4 * 4) = vl;
            }
            __syncthreads();

            // ---- MMA: per k16-step load all frags once, fire 3 split terms ----
#pragma unroll
            for (int ks = 0; ks < 4; ++ks) {
                int kw = ks * 8;
                uint32_t ah[4][4], al[4][4], bh[4][2], bl[4][2];
#pragma unroll
                for (int mi = 0; mi < 4; ++mi) {
                    const uint32_t* ph = Ah + (m0w + mi * 16 + g) * ROW_W + kw + tig;
                    const uint32_t* pl = Al + (m0w + mi * 16 + g) * ROW_W + kw + tig;
                    ah[mi][0] = ph[0];             al[mi][0] = pl[0];
                    ah[mi][1] = ph[8 * ROW_W];     al[mi][1] = pl[8 * ROW_W];
                    ah[mi][2] = ph[4];             al[mi][2] = pl[4];
                    ah[mi][3] = ph[8 * ROW_W + 4]; al[mi][3] = pl[8 * ROW_W + 4];
                }
#pragma unroll
                for (int ni = 0; ni < 4; ++ni) {
                    const uint32_t* ph = Bh + (n0w + ni * 8 + g) * ROW_W + kw + tig;
                    const uint32_t* pl = Bl + (n0w + ni * 8 + g) * ROW_W + kw + tig;
                    bh[ni][0] = ph[0]; bh[ni][1] = ph[4];
                    bl[ni][0] = pl[0]; bl[ni][1] = pl[4];
                }
#pragma unroll
                for (int mi = 0; mi < 4; ++mi)
#pragma unroll
                    for (int ni = 0; ni < 4; ++ni) {
                        mma_bf16(acc[mi][ni], ah[mi][0], ah[mi][1], ah[mi][2], ah[mi][3],
                                 bh[ni][0], bh[ni][1]);
                        mma_bf16(acc[mi][ni], ah[mi][0], ah[mi][1], ah[mi][2], ah[mi][3],
                                 bl[ni][0], bl[ni][1]);
                        mma_bf16(acc[mi][ni], al[mi][0], al[mi][1], al[mi][2], al[mi][3],
                                 bh[ni][0], bh[ni][1]);
                    }
            }
            __syncthreads();
        }
    }

    // ---- epilogue: + bias, relu, store ----
#pragma unroll
    for (int mi = 0; mi < 4; ++mi) {
        int r0 = row0 + m0w + mi * 16 + g;
        int r1 = r0 + 8;
#pragma unroll
        for (int ni = 0; ni < 4; ++ni) {
            int c = n0w + ni * 8 + 2 * tig;
            float2 bb = *(const float2*)(bias + c);
            if (r0 < NN) {
                float2 v;
                v.x = fmaxf(acc[mi][ni][0] + bb.x, 0.f);
                v.y = fmaxf(acc[mi][ni][1] + bb.y, 0.f);
                *(float2*)(Y + (size_t)r0 * D + c) = v;
            }
            if (r1 < NN) {
                float2 v;
                v.x = fmaxf(acc[mi][ni][2] + bb.x, 0.f);
                v.y = fmaxf(acc[mi][ni][3] + bb.y, 0.f);
                *(float2*)(Y + (size_t)r1 * D + c) = v;
            }
        }
    }
}

// ---------------- prediction head ----------------
__global__ void pred_kernel(const float* __restrict__ pw,
                            const float* __restrict__ pb,
                            float* __restrict__ out) {
    int warp = (blockIdx.x * blockDim.x + threadIdx.x) >> 5;
    if (warp >= NN) return;
    int lane = threadIdx.x & 31;
    float4 e = ((const float4*)(g_bufD + (size_t)warp * D))[lane];
    float4 p = __ldg((const float4*)pw + lane);
    float s = e.x * p.x + e.y * p.y + e.z * p.z + e.w * p.w;
#pragma unroll
    for (int o = 16; o; o >>= 1) s += __shfl_xor_sync(0xffffffffu, s, o);
    if (lane == 0) out[warp] = s + __ldg(pb);
}

// ---------------- host launch ----------------
extern "C" void kernel_launch(void* const* d_in, const int* in_sizes, int n_in,
                              void* d_out, int out_size) {
    const float* weights = (const float*)d_in[0];
    const int*   src     = (const int*)d_in[1];
    const int*   dst     = (const int*)d_in[2];
    const float* lin_w   = (const float*)d_in[3];
    const float* lin_b   = (const float*)d_in[4];
    const float* cheb_ws = (const float*)d_in[5];
    const float* cheb_bs = (const float*)d_in[6];
    const float* pred_w  = (const float*)d_in[7];
    const float* pred_b  = (const float*)d_in[8];
    float* out = (float*)d_out;

    cudaFuncSetAttribute(gemm_mma_kernel,
                         cudaFuncAttributeMaxDynamicSharedMemorySize, GSMEM);

    // CSR build + W pre-split
    init_kernel   <<<(NN + 255) / 256, 256>>>();
    count_kernel  <<<(NE + 255) / 256, 256>>>(dst);
    scan_kernel   <<<1, 1024>>>();
    scatter_kernel<<<(NT + 255) / 256, 256>>>(src, dst);
    wprep_kernel  <<<(3 * 384 * 128 + 255) / 256, 256>>>(cheb_ws);

    // input linear
    feat_kernel<<<(NN * (D / 4) + 255) / 256, 256>>>(weights, lin_w, lin_b);

    const int spmm_blocks = (NN * 32 + 255) / 256;   // one warp per node
    const int gemm_blocks = (NN + 127) / 128;        // 391

    for (int l = 0; l < 3; ++l) {
        int flip = (l == 1);
        spmm_kernel<<<spmm_blocks, 256>>>(0, flip);   // X1 = -A~ X0
        spmm_kernel<<<spmm_blocks, 256>>>(1, flip);   // X2 = -2 A~ X1 - X0
        gemm_mma_kernel<<<gemm_blocks, 256, GSMEM>>>(
            l, cheb_bs + (size_t)l * 128, flip);
        // inter-layer leaky_relu(relu(x)) == relu(x): no-op, skipped
    }

    pred_kernel<<<spmm_blocks, 256>>>(pred_w, pred_b, out);
}

// round 9
// speedup vs baseline: 1.9251x; 1.1829x over previous
#include <cuda_runtime.h>
#include <cuda_bf16.h>
#include <cstdint>

#define NN   50000
#define NE   600000
#define NT   (NE + NN)     // edges + self loops = 650000
#define D    128

// ---------------- device scratch (static, no runtime alloc) ----------------
// Feature ping-pong: fp32 (for SpMM gather / pred) + bf16 hi/lo (for GEMM A)
__device__ float         g_Ff[2][(size_t)NN * D];
__device__ __nv_bfloat16 g_Fh[2][(size_t)NN * D];
__device__ __nv_bfloat16 g_Fl[2][(size_t)NN * D];
__device__ float         g_P1f[(size_t)NN * D];
__device__ __nv_bfloat16 g_P1h[(size_t)NN * D];
__device__ __nv_bfloat16 g_P1l[(size_t)NN * D];
__device__ __nv_bfloat16 g_P2h[(size_t)NN * D];
__device__ __nv_bfloat16 g_P2l[(size_t)NN * D];
__device__ int2  g_colew[NT];            // packed {col, bitcast(weight)}
__device__ int   g_rowptr[NN + 1];
__device__ int   g_deg[NN];              // zero-init at load; scan self-resets
__device__ int   g_cursor[NN];
__device__ float g_dinv[NN];
// Folded W (W0-W2, -W1, 2*W2) as bf16 hi/lo, transposed: [layer][n(128)][k(384)]
__device__ __nv_bfloat16 g_Whi[3 * 128 * 384];
__device__ __nv_bfloat16 g_Wlo[3 * 128 * 384];

// ---------------- helpers ----------------
__device__ __forceinline__ uint32_t pack2(float a, float b) {
    __nv_bfloat162 h = __floats2bfloat162_rn(a, b);
    return *reinterpret_cast<uint32_t*>(&h);
}

#define CP16(daddr, gptr) \
    asm volatile("cp.async.cg.shared.global [%0], [%1], 16;" \
        :: "r"(daddr), "l"(gptr))
#define CP_COMMIT() asm volatile("cp.async.commit_group;" ::: "memory")
#define CP_WAIT(n)  asm volatile("cp.async.wait_group %0;" :: "n"(n) : "memory")

// ---------------- CSR build ----------------
__global__ void count_kernel(const int* __restrict__ dst) {
    int e = blockIdx.x * blockDim.x + threadIdx.x;
    if (e < NE) atomicAdd(&g_deg[dst[e]], 1);
}

// single-block scan with smem staging; self-resets deg/cursor for next replay
__global__ void scan_kernel() {
    extern __shared__ int ssm[];            // NN ints
    __shared__ int part[1024];
    const int T = 1024;
    const int CHUNK = (NN + T - 1) / T;     // 49
    int tid = threadIdx.x;

    // coalesced load (deg+1 for self loop) + reset globals for next run
    for (int i = tid; i < NN; i += T) {
        ssm[i] = g_deg[i] + 1;
        g_deg[i] = 0;
        g_cursor[i] = 0;
    }
    __syncthreads();

    int start = tid * CHUNK;
    int end = start + CHUNK; if (end > NN) end = NN;
    int s = 0;
    for (int i = start; i < end; ++i) s += ssm[i];
    part[tid] = s;
    __syncthreads();
    for (int off = 1; off < T; off <<= 1) {
        int v = (tid >= off) ? part[tid - off] : 0;
        __syncthreads();
        part[tid] += v;
        __syncthreads();
    }
    int run = part[tid] - s;                // exclusive prefix
    for (int i = start; i < end; ++i) {
        int v = ssm[i];
        ssm[i] = run;
        run += v;
    }
    __syncthreads();
    int total = part[T - 1];
    for (int i = tid; i < NN; i += T) {     // coalesced writeout
        int rp = ssm[i];
        g_rowptr[i] = rp;
        int nxt = (i + 1 < NN) ? ssm[i + 1] : total;
        g_dinv[i] = rsqrtf((float)(nxt - rp));
    }
    if (tid == 0) g_rowptr[NN] = total;
}

__global__ void scatter_kernel(const int* __restrict__ src, const int* __restrict__ dst) {
    int e = blockIdx.x * blockDim.x + threadIdx.x;
    if (e >= NT) return;
    int s, d;
    if (e < NE) { s = src[e]; d = dst[e]; }
    else        { s = d = e - NE; }
    int pos = g_rowptr[d] + atomicAdd(&g_cursor[d], 1);
    g_colew[pos] = make_int2(s, __float_as_int(g_dinv[s] * g_dinv[d]));
}

// ---------------- W fold + bf16 hi/lo split, transposed ----------------
// Y = relu(X0*(W0-W2) + P1*(-W1) + P2*(2*W2) + b)
__global__ void wprep_kernel(const float* __restrict__ cheb_ws) {
    int i = blockIdx.x * blockDim.x + threadIdx.x;   // 3*384*128
    if (i >= 3 * 384 * 128) return;
    int l   = i / (384 * 128);
    int rem = i % (384 * 128);
    int k = rem >> 7;      // 0..383
    int n = rem & 127;
    int seg = k >> 7;      // 0,1,2
    int kin = k & 127;
    const float* WL0 = cheb_ws + (size_t)l * 384 * 128;
    float w;
    if (seg == 0)      w = __ldg(WL0 + (size_t)k * 128 + n) - __ldg(WL0 + (size_t)(256 + kin) * 128 + n);
    else if (seg == 1) w = -__ldg(WL0 + (size_t)k * 128 + n);
    else               w = 2.0f * __ldg(WL0 + (size_t)k * 128 + n);
    __nv_bfloat16 h = __float2bfloat16_rn(w);
    size_t o = ((size_t)l * 128 + n) * 384 + k;
    g_Whi[o] = h;
    g_Wlo[o] = __float2bfloat16_rn(w - __bfloat162float(h));
}

// ---------------- input linear: feat = w * lin_w + lin_b (+ hi/lo) ----------------
__global__ void feat_kernel(const float* __restrict__ w,
                            const float* __restrict__ lw,
                            const float* __restrict__ lb) {
    int i = blockIdx.x * blockDim.x + threadIdx.x;
    if (i >= NN * (D / 4)) return;
    int v  = i >> 5;
    int d4 = i & 31;
    float s = __ldg(w + v);
    float4 a = __ldg((const float4*)lw + d4);
    float4 b = __ldg((const float4*)lb + d4);
    float4 r;
    r.x = fmaf(s, a.x, b.x); r.y = fmaf(s, a.y, b.y);
    r.z = fmaf(s, a.z, b.z); r.w = fmaf(s, a.w, b.w);
    ((float4*)g_Ff[0])[i] = r;
    __nv_bfloat16 h0 = __float2bfloat16_rn(r.x);
    __nv_bfloat16 h1 = __float2bfloat16_rn(r.y);
    __nv_bfloat16 h2 = __float2bfloat16_rn(r.z);
    __nv_bfloat16 h3 = __float2bfloat16_rn(r.w);
    uint2 hv = make_uint2(pack2(__bfloat162float(h0), __bfloat162float(h1)),
                          pack2(__bfloat162float(h2), __bfloat162float(h3)));
    uint2 lv = make_uint2(pack2(r.x - __bfloat162float(h0), r.y - __bfloat162float(h1)),
                          pack2(r.z - __bfloat162float(h2), r.w - __bfloat162float(h3)));
    *(uint2*)(g_Fh[0] + (size_t)i * 4) = hv;
    *(uint2*)(g_Fl[0] + (size_t)i * 4) = lv;
}

// ---------------- SpMM: out = A_norm @ X (pure), epilogue emits fp32 + hi/lo ----
__global__ void spmm_kernel(int mode, int flip) {
    const float* X = (mode == 0) ? g_Ff[flip] : g_P1f;

    int warp = (blockIdx.x * blockDim.x + threadIdx.x) >> 5;
    if (warp >= NN) return;
    int lane = threadIdx.x & 31;
    int beg = g_rowptr[warp];
    int end = g_rowptr[warp + 1];

    float4 acc = make_float4(0.f, 0.f, 0.f, 0.f);
    int p = beg;
    for (; p + 3 < end; p += 4) {
        int2 e0 = __ldg(g_colew + p);
        int2 e1 = __ldg(g_colew + p + 1);
        int2 e2 = __ldg(g_colew + p + 2);
        int2 e3 = __ldg(g_colew + p + 3);
        float4 x0 = __ldg((const float4*)(X + (size_t)e0.x * D) + lane);
        float4 x1 = __ldg((const float4*)(X + (size_t)e1.x * D) + lane);
        float4 x2 = __ldg((const float4*)(X + (size_t)e2.x * D) + lane);
        float4 x3 = __ldg((const float4*)(X + (size_t)e3.x * D) + lane);
        float w0 = __int_as_float(e0.y);
        float w1 = __int_as_float(e1.y);
        float w2 = __int_as_float(e2.y);
        float w3 = __int_as_float(e3.y);
        acc.x = fmaf(w0, x0.x, acc.x); acc.y = fmaf(w0, x0.y, acc.y);
        acc.z = fmaf(w0, x0.z, acc.z); acc.w = fmaf(w0, x0.w, acc.w);
        acc.x = fmaf(w1, x1.x, acc.x); acc.y = fmaf(w1, x1.y, acc.y);
        acc.z = fmaf(w1, x1.z, acc.z); acc.w = fmaf(w1, x1.w, acc.w);
        acc.x = fmaf(w2, x2.x, acc.x); acc.y = fmaf(w2, x2.y, acc.y);
        acc.z = fmaf(w2, x2.z, acc.z); acc.w = fmaf(w2, x2.w, acc.w);
        acc.x = fmaf(w3, x3.x, acc.x); acc.y = fmaf(w3, x3.y, acc.y);
        acc.z = fmaf(w3, x3.z, acc.z); acc.w = fmaf(w3, x3.w, acc.w);
    }
    for (; p < end; ++p) {
        int2 e0 = __ldg(g_colew + p);
        float w0 = __int_as_float(e0.y);
        float4 x0 = __ldg((const float4*)(X + (size_t)e0.x * D) + lane);
        acc.x = fmaf(w0, x0.x, acc.x); acc.y = fmaf(w0, x0.y, acc.y);
        acc.z = fmaf(w0, x0.z, acc.z); acc.w = fmaf(w0, x0.w, acc.w);
    }

    __nv_bfloat16 h0 = __float2bfloat16_rn(acc.x);
    __nv_bfloat16 h1 = __float2bfloat16_rn(acc.y);
    __nv_bfloat16 h2 = __float2bfloat16_rn(acc.z);
    __nv_bfloat16 h3 = __float2bfloat16_rn(acc.w);
    uint2 hv = make_uint2(pack2(__bfloat162float(h0), __bfloat162float(h1)),
                          pack2(__bfloat162float(h2), __bfloat162float(h3)));
    uint2 lv = make_uint2(pack2(acc.x - __bfloat162float(h0), acc.y - __bfloat162float(h1)),
                          pack2(acc.z - __bfloat162float(h2), acc.w - __bfloat162float(h3)));
    size_t eo = (size_t)warp * D + lane * 4;
    if (mode == 0) {
        ((float4*)(g_P1f + (size_t)warp * D))[lane] = acc;
        *(uint2*)(g_P1h + eo) = hv;
        *(uint2*)(g_P1l + eo) = lv;
    } else {
        *(uint2*)(g_P2h + eo) = hv;
        *(uint2*)(g_P2l + eo) = lv;
    }
}

// ======================= mma.sync bf16 GEMM (3-term split) =======================
// Y = relu(X0*W0' + P1*W1' + P2*W2' + b); all operands pre-split bf16 hi/lo.
// 8 warps, warp tile 64x32, m16n8k16. 6 chunks of K=64, double-buffered cp.async.
// Smem rows padded to 36 words (72 bf16) -> conflict-free fragment LDS.

#define ROW_W     36
#define BUF_W     (128 * ROW_W)           // words per sub-buffer
#define BUF_BYTES (BUF_W * 4)             // 18432
#define CH_BYTES  (4 * BUF_BYTES)         // 73728 (Ah,Al,Bh,Bl)
#define GSMEM     (2 * CH_BYTES)          // 147456 dynamic smem

__device__ __forceinline__ void mma_bf16(float* acc,
                                         uint32_t a0, uint32_t a1, uint32_t a2, uint32_t a3,
                                         uint32_t b0, uint32_t b1) {
    asm volatile(
        "mma.sync.aligned.m16n8k16.row.col.f32.bf16.bf16.f32 "
        "{%0,%1,%2,%3}, {%4,%5,%6,%7}, {%8,%9}, {%0,%1,%2,%3};"
        : "+f"(acc[0]), "+f"(acc[1]), "+f"(acc[2]), "+f"(acc[3])
        : "r"(a0), "r"(a1), "r"(a2), "r"(a3), "r"(b0), "r"(b1));
}

__device__ __forceinline__ void issue_chunk(
    uint32_t bb,                           // smem byte addr of chunk buffer
    const __nv_bfloat16* __restrict__ Xh, const __nv_bfloat16* __restrict__ Xl,
    const __nv_bfloat16* __restrict__ WH, const __nv_bfloat16* __restrict__ WL,
    int row0, int kk, int kbase, int tid)
{
#pragma unroll
    for (int i = 0; i < 4; ++i) {
        int idx = tid + i * 256;
        int r = idx >> 3, f = idx & 7;
        int grow = row0 + r; if (grow >= NN) grow = NN - 1;   // OOB rows discarded later
        CP16(bb + (uint32_t)(r * ROW_W + f * 4) * 4,
             Xh + (size_t)grow * D + kk + f * 8);
    }
#pragma unroll
    for (int i = 0; i < 4; ++i) {
        int idx = tid + i * 256;
        int r = idx >> 3, f = idx & 7;
        int grow = row0 + r; if (grow >= NN) grow = NN - 1;
        CP16(bb + BUF_BYTES + (uint32_t)(r * ROW_W + f * 4) * 4,
             Xl + (size_t)grow * D + kk + f * 8);
    }
#pragma unroll
    for (int i = 0; i < 4; ++i) {
        int idx = tid + i * 256;
        int n = idx >> 3, f = idx & 7;
        CP16(bb + 2 * BUF_BYTES + (uint32_t)(n * ROW_W + f * 4) * 4,
             WH + (size_t)n * 384 + kbase + f * 8);
    }
#pragma unroll
    for (int i = 0; i < 4; ++i) {
        int idx = tid + i * 256;
        int n = idx >> 3, f = idx & 7;
        CP16(bb + 3 * BUF_BYTES + (uint32_t)(n * ROW_W + f * 4) * 4,
             WL + (size_t)n * 384 + kbase + f * 8);
    }
}

__global__ __launch_bounds__(256, 1)
void gemm_mma_kernel(int layer, const float* __restrict__ bias, int flip) {
    extern __shared__ uint32_t dsm[];
    uint32_t sbase = (uint32_t)__cvta_generic_to_shared(dsm);

    const __nv_bfloat16* AH0 = g_Fh[flip];
    const __nv_bfloat16* AL0 = g_Fl[flip];
    float*         Yf = g_Ff[flip ^ 1];
    __nv_bfloat16* Yh = g_Fh[flip ^ 1];
    __nv_bfloat16* Yl = g_Fl[flip ^ 1];
    const __nv_bfloat16* WH = g_Whi + (size_t)layer * 128 * 384;
    const __nv_bfloat16* WL = g_Wlo + (size_t)layer * 128 * 384;

    int tid = threadIdx.x;
    int wid = tid >> 5;
    int lane = tid & 31;
    int g   = lane >> 2;
    int tig = lane & 3;
    int row0 = blockIdx.x * 128;

    int m0w = (wid >> 2) * 64;
    int n0w = (wid & 3) * 32;

    float acc[4][4][4];
#pragma unroll
    for (int mi = 0; mi < 4; ++mi)
#pragma unroll
        for (int ni = 0; ni < 4; ++ni)
#pragma unroll
            for (int q = 0; q < 4; ++q) acc[mi][ni][q] = 0.f;

    // prologue: chunk 0 into buffer 0
    issue_chunk(sbase, AH0, AL0, WH, WL, row0, 0, 0, tid);
    CP_COMMIT();

    for (int c = 0; c < 6; ++c) {
        if (c < 5) {
            int nc = c + 1;
            int srcI = nc >> 1, kk = (nc & 1) * 64;
            const __nv_bfloat16* Xh = (srcI == 0) ? AH0 : ((srcI == 1) ? g_P1h : g_P2h);
            const __nv_bfloat16* Xl = (srcI == 0) ? AL0 : ((srcI == 1) ? g_P1l : g_P2l);
            issue_chunk(sbase + (uint32_t)(nc & 1) * CH_BYTES,
                        Xh, Xl, WH, WL, row0, kk, srcI * 128 + kk, tid);
            CP_COMMIT();
            CP_WAIT(1);
        } else {
            CP_WAIT(0);
        }
        __syncthreads();

        const uint32_t* Ah = dsm + (size_t)(c & 1) * (4 * BUF_W);
        const uint32_t* Al = Ah + BUF_W;
        const uint32_t* Bh = Ah + 2 * BUF_W;
        const uint32_t* Bl = Ah + 3 * BUF_W;

#pragma unroll
        for (int ks = 0; ks < 4; ++ks) {
            int kw = ks * 8;
            uint32_t ah[4][4], al[4][4], bh[4][2], bl[4][2];
#pragma unroll
            for (int mi = 0; mi < 4; ++mi) {
                const uint32_t* ph = Ah + (m0w + mi * 16 + g) * ROW_W + kw + tig;
                const uint32_t* pl = Al + (m0w + mi * 16 + g) * ROW_W + kw + tig;
                ah[mi][0] = ph[0];             al[mi][0] = pl[0];
                ah[mi][1] = ph[8 * ROW_W];     al[mi][1] = pl[8 * ROW_W];
                ah[mi][2] = ph[4];             al[mi][2] = pl[4];
                ah[mi][3] = ph[8 * ROW_W + 4]; al[mi][3] = pl[8 * ROW_W + 4];
            }
#pragma unroll
            for (int ni = 0; ni < 4; ++ni) {
                const uint32_t* ph = Bh + (n0w + ni * 8 + g) * ROW_W + kw + tig;
                const uint32_t* pl = Bl + (n0w + ni * 8 + g) * ROW_W + kw + tig;
                bh[ni][0] = ph[0]; bh[ni][1] = ph[4];
                bl[ni][0] = pl[0]; bl[ni][1] = pl[4];
            }
#pragma unroll
            for (int mi = 0; mi < 4; ++mi)
#pragma unroll
                for (int ni = 0; ni < 4; ++ni) {
                    mma_bf16(acc[mi][ni], ah[mi][0], ah[mi][1], ah[mi][2], ah[mi][3],
                             bh[ni][0], bh[ni][1]);
                    mma_bf16(acc[mi][ni], ah[mi][0], ah[mi][1], ah[mi][2], ah[mi][3],
                             bl[ni][0], bl[ni][1]);
                    mma_bf16(acc[mi][ni], al[mi][0], al[mi][1], al[mi][2], al[mi][3],
                             bh[ni][0], bh[ni][1]);
                }
        }
        __syncthreads();
    }

    // ---- epilogue: + bias, relu, store fp32 + bf16 hi/lo ----
#pragma unroll
    for (int mi = 0; mi < 4; ++mi) {
        int r0 = row0 + m0w + mi * 16 + g;
        int r1 = r0 + 8;
#pragma unroll
        for (int ni = 0; ni < 4; ++ni) {
            int c = n0w + ni * 8 + 2 * tig;
            float2 bb = *(const float2*)(bias + c);
            if (r0 < NN) {
                float2 v;
                v.x = fmaxf(acc[mi][ni][0] + bb.x, 0.f);
                v.y = fmaxf(acc[mi][ni][1] + bb.y, 0.f);
                *(float2*)(Yf + (size_t)r0 * D + c) = v;
                __nv_bfloat16 h0 = __float2bfloat16_rn(v.x);
                __nv_bfloat16 h1 = __float2bfloat16_rn(v.y);
                *(uint32_t*)(Yh + (size_t)r0 * D + c) =
                    pack2(__bfloat162float(h0), __bfloat162float(h1));
                *(uint32_t*)(Yl + (size_t)r0 * D + c) =
                    pack2(v.x - __bfloat162float(h0), v.y - __bfloat162float(h1));
            }
            if (r1 < NN) {
                float2 v;
                v.x = fmaxf(acc[mi][ni][2] + bb.x, 0.f);
                v.y = fmaxf(acc[mi][ni][3] + bb.y, 0.f);
                *(float2*)(Yf + (size_t)r1 * D + c) = v;
                __nv_bfloat16 h0 = __float2bfloat16_rn(v.x);
                __nv_bfloat16 h1 = __float2bfloat16_rn(v.y);
                *(uint32_t*)(Yh + (size_t)r1 * D + c) =
                    pack2(__bfloat162float(h0), __bfloat162float(h1));
                *(uint32_t*)(Yl + (size_t)r1 * D + c) =
                    pack2(v.x - __bfloat162float(h0), v.y - __bfloat162float(h1));
            }
        }
    }
}

// ---------------- prediction head ----------------
__global__ void pred_kernel(const float* __restrict__ pw,
                            const float* __restrict__ pb,
                            float* __restrict__ out) {
    int warp = (blockIdx.x * blockDim.x + threadIdx.x) >> 5;
    if (warp >= NN) return;
    int lane = threadIdx.x & 31;
    float4 e = ((const float4*)(g_Ff[1] + (size_t)warp * D))[lane];
    float4 p = __ldg((const float4*)pw + lane);
    float s = e.x * p.x + e.y * p.y + e.z * p.z + e.w * p.w;
#pragma unroll
    for (int o = 16; o; o >>= 1) s += __shfl_xor_sync(0xffffffffu, s, o);
    if (lane == 0) out[warp] = s + __ldg(pb);
}

// ---------------- host launch ----------------
extern "C" void kernel_launch(void* const* d_in, const int* in_sizes, int n_in,
                              void* d_out, int out_size) {
    const float* weights = (const float*)d_in[0];
    const int*   src     = (const int*)d_in[1];
    const int*   dst     = (const int*)d_in[2];
    const float* lin_w   = (const float*)d_in[3];
    const float* lin_b   = (const float*)d_in[4];
    const float* cheb_ws = (const float*)d_in[5];
    const float* cheb_bs = (const float*)d_in[6];
    const float* pred_w  = (const float*)d_in[7];
    const float* pred_b  = (const float*)d_in[8];
    float* out = (float*)d_out;

    cudaFuncSetAttribute(gemm_mma_kernel,
                         cudaFuncAttributeMaxDynamicSharedMemorySize, GSMEM);
    cudaFuncSetAttribute(scan_kernel,
                         cudaFuncAttributeMaxDynamicSharedMemorySize, NN * 4);

    // CSR build (init fused into self-resetting scan) + W fold/pre-split
    count_kernel  <<<(NE + 255) / 256, 256>>>(dst);
    scan_kernel   <<<1, 1024, NN * 4>>>();
    scatter_kernel<<<(NT + 255) / 256, 256>>>(src, dst);
    wprep_kernel  <<<(3 * 384 * 128 + 255) / 256, 256>>>(cheb_ws);

    // input linear
    feat_kernel<<<(NN * (D / 4) + 255) / 256, 256>>>(weights, lin_w, lin_b);

    const int spmm_blocks = (NN * 32 + 255) / 256;   // one warp per node
    const int gemm_blocks = (NN + 127) / 128;        // 391

    for (int l = 0; l < 3; ++l) {
        int flip = l & 1;
        spmm_kernel<<<spmm_blocks, 256>>>(0, flip);   // P1 = A~ X0
        spmm_kernel<<<spmm_blocks, 256>>>(1, flip);   // P2 = A~ P1
        gemm_mma_kernel<<<gemm_blocks, 256, GSMEM>>>(
            l, cheb_bs + (size_t)l * 128, flip);
        // inter-layer leaky_relu(relu(x)) == relu(x): no-op, skipped
    }

    pred_kernel<<<spmm_blocks, 256>>>(pred_w, pred_b, out);
}